// round 13
// baseline (speedup 1.0000x reference)
#include <cuda_runtime.h>
#include <cuda_bf16.h>
#include <math.h>
#include <cstdint>

// Problem dims
#define Bv 128
#define Tv 1024
#define Iv 512
#define Hv 1024
#define Ov 256

#define NBLK_SCAN 256   // 16 k-chunks x 16 n-tiles, 2 CTAs/SM
#define KCHUNKS   16

typedef unsigned long long ull;

// -------- scratch (device globals: no allocation allowed) --------
__device__ __nv_bfloat16 g_xh[(size_t)Tv * Bv * Iv]; // x split hi, [t][b][i]
__device__ __nv_bfloat16 g_xl[(size_t)Tv * Bv * Iv]; // x split lo, [t][b][i]
__device__ __nv_bfloat16 g_hh[Bv * Hv];              // hidden state, bf16 hi
__device__ __nv_bfloat16 g_hl[Bv * Hv];              // hidden state, bf16 lo
__device__ float g_part[KCHUNKS][Bv * Hv];           // split-K partials (8 MB)
__device__ unsigned g_bar_count;
__device__ volatile unsigned g_bar_gen;

// -------- mma.sync / ldmatrix helpers --------
__device__ __forceinline__ uint32_t smem_u32(const void* p) {
    uint32_t a;
    asm("{ .reg .u64 t; cvta.to.shared.u64 t, %1; cvt.u32.u64 %0, t; }"
        : "=r"(a) : "l"(p));
    return a;
}
__device__ __forceinline__ void ldsm4(uint32_t r[4], uint32_t addr) {
    asm volatile("ldmatrix.sync.aligned.m8n8.x4.shared.b16 {%0,%1,%2,%3}, [%4];"
                 : "=r"(r[0]), "=r"(r[1]), "=r"(r[2]), "=r"(r[3]) : "r"(addr));
}
__device__ __forceinline__ void mma_bf16(float d[4], const uint32_t a[4],
                                         const uint32_t b0, const uint32_t b1) {
    asm volatile(
        "mma.sync.aligned.m16n8k16.row.col.f32.bf16.bf16.f32 "
        "{%0,%1,%2,%3}, {%4,%5,%6,%7}, {%8,%9}, {%0,%1,%2,%3};"
        : "+f"(d[0]), "+f"(d[1]), "+f"(d[2]), "+f"(d[3])
        : "r"(a[0]), "r"(a[1]), "r"(a[2]), "r"(a[3]), "r"(b0), "r"(b1));
}
__device__ __forceinline__ uint32_t bf16pack(float a, float b) {
    __nv_bfloat16 x = __float2bfloat16(a);
    __nv_bfloat16 y = __float2bfloat16(b);
    return (uint32_t)__bfloat16_as_ushort(x) |
           ((uint32_t)__bfloat16_as_ushort(y) << 16);
}

// ============================================================
// Kernel 0: split x into bf16 hi/lo, transpose [b][t][i] -> [t][b][i]
// ============================================================
__global__ void __launch_bounds__(256) split_x(const float* __restrict__ X)
{
    size_t idx8 = (size_t)blockIdx.x * 256 + threadIdx.x;
    if (idx8 >= (size_t)Bv * Tv * Iv / 8) return;
    int i = (int)(idx8 & 63) * 8;
    int t = (int)((idx8 >> 6) & 1023);
    int b = (int)(idx8 >> 16);

    const float* src = X + (((size_t)b * Tv + t) * Iv + i);
    float4 f0 = *(const float4*)(src + 0);
    float4 f1 = *(const float4*)(src + 4);
    float f[8] = {f0.x, f0.y, f0.z, f0.w, f1.x, f1.y, f1.z, f1.w};

    uint32_t hi[4], lo[4];
#pragma unroll
    for (int j = 0; j < 4; j++) {
        __nv_bfloat16 h0 = __float2bfloat16(f[2 * j]);
        __nv_bfloat16 h1 = __float2bfloat16(f[2 * j + 1]);
        hi[j] = (uint32_t)__bfloat16_as_ushort(h0) |
                ((uint32_t)__bfloat16_as_ushort(h1) << 16);
        lo[j] = bf16pack(f[2 * j] - __bfloat162float(h0),
                         f[2 * j + 1] - __bfloat162float(h1));
    }
    size_t o = (((size_t)t * Bv + b) * Iv + i);
    *(uint4*)&g_xh[o] = *(const uint4*)hi;
    *(uint4*)&g_xl[o] = *(const uint4*)lo;
}

// ============================================================
// Kernel B: persistent fused scan, 256 CTAs (2/SM), kc16 x nt16.
// CTA (kc,nt): part[kc][:, nt*64..+64] = h @ Wr[kc*64 slice] + x[t] @ Wk[kc*32 slice]
// SMEM 96KB/CTA: Ahh 16K | Ahl 16K | Bwh 8K | Bwl 8K | Xhh 16K | Xhl 16K | Kwh 8K | Kwl 8K
// (X/Kw rows padded to 128B; same proven swizzle everywhere)
// ============================================================
__global__ void __launch_bounds__(256, 2) scan_kernel(
    const float* __restrict__ WR, const float* __restrict__ WK,
    const float* __restrict__ bias)
{
    extern __shared__ __align__(1024) char smem[];
    char* sAhh = smem;                     // 16384
    char* sAhl = smem + 16384;             // 16384
    char* sBwh = smem + 32768;             // 8192
    char* sBwl = smem + 40960;             // 8192
    char* sXhh = smem + 49152;             // 16384
    char* sXhl = smem + 65536;             // 16384
    char* sKwh = smem + 81920;             // 8192
    char* sKwl = smem + 90112;             // 8192
    const uint32_t pAhh = smem_u32(smem);
    const uint32_t pAhl = pAhh + 16384;
    const uint32_t pBwh = pAhh + 32768;
    const uint32_t pBwl = pAhh + 40960;
    const uint32_t pXhh = pAhh + 49152;
    const uint32_t pXhl = pAhh + 65536;
    const uint32_t pKwh = pAhh + 81920;
    const uint32_t pKwl = pAhh + 90112;

    const int tid = threadIdx.x;
    const int wid = tid >> 5;
    const int lid = tid & 31;
    const int bi = blockIdx.x;
    const int kc = bi >> 4;            // 0..15
    const int nt = bi & 15;            // 0..15
    const int kbase = kc * 64;         // Wr K slice
    const int xbase = kc * 32;         // Wk K slice
    const int nbase = nt * 64;
    // reduce ownership: threads 0..127 each own 4 elems
    const int e = (bi * 128 + (tid & 127)) * 4;

    const int wm = wid & 1;            // M: 2 x 64
    const int wn = wid >> 1;           // N: 4 x 16

    // ldmatrix lane invariants (R7-proven)
    const int rowA = ((lid >> 3) & 1) * 8 + (lid & 7);
    const int khA  = (lid >> 4) * 16;
    const int rowB = ((lid >> 4) & 1) * 8 + (lid & 7);
    const int khB  = ((lid >> 3) & 1) * 16;
    const int sw   = (lid & 7) << 4;
    const uint32_t aHiBase = pAhh + (wm * 64 + rowA) * 128;
    const uint32_t aLoBase = pAhl + (wm * 64 + rowA) * 128;
    const uint32_t bHiBase = pBwh + (wn * 16 + rowB) * 128;
    const uint32_t bLoBase = pBwl + (wn * 16 + rowB) * 128;
    const uint32_t xHiBase = pXhh + (wm * 64 + rowA) * 128;
    const uint32_t xLoBase = pXhl + (wm * 64 + rowA) * 128;
    const uint32_t kHiBase = pKwh + (wn * 16 + rowB) * 128;
    const uint32_t kLoBase = pKwl + (wn * 16 + rowB) * 128;

    // ---- preload Wr slice: [n 0..63][k 0..63], swizzled ----
    for (int idx = tid; idx < 64 * 64; idx += 256) {
        int n = idx & 63;
        int k = idx >> 6;
        float w = WR[(size_t)(kbase + k) * Hv + nbase + n];
        __nv_bfloat16 wh = __float2bfloat16(w);
        __nv_bfloat16 wl = __float2bfloat16(w - __bfloat162float(wh));
        uint32_t off = n * 128 + ((k * 2) ^ ((n & 7) << 4));
        *(__nv_bfloat16*)(sBwh + off) = wh;
        *(__nv_bfloat16*)(sBwl + off) = wl;
    }
    // ---- preload Wk slice: [n 0..63][k 0..31], padded 128B rows ----
    for (int idx = tid; idx < 64 * 32; idx += 256) {
        int n = idx & 63;
        int k = idx >> 6;
        float w = WK[(size_t)(xbase + k) * Hv + nbase + n];
        __nv_bfloat16 wh = __float2bfloat16(w);
        __nv_bfloat16 wl = __float2bfloat16(w - __bfloat162float(wh));
        uint32_t off = n * 128 + ((k * 2) ^ ((n & 7) << 4));
        *(__nv_bfloat16*)(sKwh + off) = wh;
        *(__nv_bfloat16*)(sKwl + off) = wl;
    }

    // zero initial hidden state (threads 0..127 own 4 elems each)
    if (tid < 128) {
        *(ull*)&g_hh[e] = 0ull;
        *(ull*)&g_hl[e] = 0ull;
    }

    float4 bb;
    {
        int col = e & (Hv - 1);
        bb = *(const float4*)&bias[col];
    }

    const int srow = tid >> 1;
    const int shalf = tid & 1;
    const uint32_t rb = srow * 128;
    const uint32_t sws = (srow & 7) << 4;
    const uint32_t soff = shalf * 64;      // A: 64B half of 128B row
    const uint32_t xsoff = shalf * 32;     // X: 32B half of 64B used

    // ---- stage x[0] tile (K=32) ----
    {
        const char* xh = (const char*)(g_xh + (size_t)srow * Iv + xbase) + xsoff;
        const char* xl = (const char*)(g_xl + (size_t)srow * Iv + xbase) + xsoff;
#pragma unroll
        for (int j = 0; j < 2; j++) {
            uint4 a = __ldcg((const uint4*)xh + j);
            uint4 b = __ldcg((const uint4*)xl + j);
            *(uint4*)(sXhh + rb + ((xsoff + j * 16) ^ sws)) = a;
            *(uint4*)(sXhl + rb + ((xsoff + j * 16) ^ sws)) = b;
        }
    }

    // ---- initial barrier (R10 flat) ----
    __threadfence();
    __syncthreads();
    if (tid == 0) {
        unsigned gen = g_bar_gen;
        unsigned prev = atomicAdd(&g_bar_count, 1u);
        if (prev == NBLK_SCAN - 1) { g_bar_count = 0; __threadfence(); g_bar_gen = gen + 1; }
        else { while (g_bar_gen == gen) {} }
    }
    __syncthreads();

#pragma unroll 1
    for (int t = 0; t < Tv; t++) {
        // ---- stage h slice (K=64, bf16 hi/lo, swizzled) ----
        {
            const char* sh = (const char*)(g_hh + (size_t)srow * Hv + kbase) + soff;
            const char* sl = (const char*)(g_hl + (size_t)srow * Hv + kbase) + soff;
            uint4 h0 = __ldcg((const uint4*)sh + 0);
            uint4 h1 = __ldcg((const uint4*)sh + 1);
            uint4 h2 = __ldcg((const uint4*)sh + 2);
            uint4 h3 = __ldcg((const uint4*)sh + 3);
            uint4 l0 = __ldcg((const uint4*)sl + 0);
            uint4 l1 = __ldcg((const uint4*)sl + 1);
            uint4 l2 = __ldcg((const uint4*)sl + 2);
            uint4 l3 = __ldcg((const uint4*)sl + 3);
            *(uint4*)(sAhh + rb + ((soff +  0) ^ sws)) = h0;
            *(uint4*)(sAhh + rb + ((soff + 16) ^ sws)) = h1;
            *(uint4*)(sAhh + rb + ((soff + 32) ^ sws)) = h2;
            *(uint4*)(sAhh + rb + ((soff + 48) ^ sws)) = h3;
            *(uint4*)(sAhl + rb + ((soff +  0) ^ sws)) = l0;
            *(uint4*)(sAhl + rb + ((soff + 16) ^ sws)) = l1;
            *(uint4*)(sAhl + rb + ((soff + 32) ^ sws)) = l2;
            *(uint4*)(sAhl + rb + ((soff + 48) ^ sws)) = l3;
        }
        __syncthreads();

        // ---- GEMM: rec (K=64, 4 ks) + xp (K=32, 2 ks), 3-term each ----
        float D[4][2][4];
#pragma unroll
        for (int i = 0; i < 4; i++)
#pragma unroll
            for (int j = 0; j < 2; j++)
#pragma unroll
                for (int q = 0; q < 4; q++) D[i][j][q] = 0.f;

#pragma unroll
        for (int ks = 0; ks < 4; ks++) {
            const uint32_t koffA = ((ks * 32) | khA) ^ sw;
            const uint32_t koffB = ((ks * 32) | khB) ^ sw;
            uint32_t Ah[4][4], Al[4][4], Bh[4], Bl[4];
#pragma unroll
            for (int mt = 0; mt < 4; mt++) {
                ldsm4(Ah[mt], aHiBase + mt * 2048 + koffA);
                ldsm4(Al[mt], aLoBase + mt * 2048 + koffA);
            }
            ldsm4(Bh, bHiBase + koffB);
            ldsm4(Bl, bLoBase + koffB);
#pragma unroll
            for (int mt = 0; mt < 4; mt++) {
#pragma unroll
                for (int ntl = 0; ntl < 2; ntl++) {
                    const int q = ntl * 2;
                    mma_bf16(D[mt][ntl], Ah[mt], Bh[q], Bh[q + 1]);
                    mma_bf16(D[mt][ntl], Al[mt], Bh[q], Bh[q + 1]);
                    mma_bf16(D[mt][ntl], Ah[mt], Bl[q], Bl[q + 1]);
                }
            }
        }
#pragma unroll
        for (int ks = 0; ks < 2; ks++) {
            const uint32_t koffA = ((ks * 32) | khA) ^ sw;
            const uint32_t koffB = ((ks * 32) | khB) ^ sw;
            uint32_t Ah[4][4], Al[4][4], Bh[4], Bl[4];
#pragma unroll
            for (int mt = 0; mt < 4; mt++) {
                ldsm4(Ah[mt], xHiBase + mt * 2048 + koffA);
                ldsm4(Al[mt], xLoBase + mt * 2048 + koffA);
            }
            ldsm4(Bh, kHiBase + koffB);
            ldsm4(Bl, kLoBase + koffB);
#pragma unroll
            for (int mt = 0; mt < 4; mt++) {
#pragma unroll
                for (int ntl = 0; ntl < 2; ntl++) {
                    const int q = ntl * 2;
                    mma_bf16(D[mt][ntl], Ah[mt], Bh[q], Bh[q + 1]);
                    mma_bf16(D[mt][ntl], Al[mt], Bh[q], Bh[q + 1]);
                    mma_bf16(D[mt][ntl], Ah[mt], Bl[q], Bl[q + 1]);
                }
            }
        }

        // ---- write split-K partials ----
        {
            const int g = lid >> 2, c2 = (lid & 3) * 2;
            float* P = g_part[kc];
#pragma unroll
            for (int mt = 0; mt < 4; mt++) {
#pragma unroll
                for (int ntl = 0; ntl < 2; ntl++) {
                    int row0 = wm * 64 + mt * 16 + g;
                    int col = nbase + wn * 16 + ntl * 8 + c2;
                    float2 v0 = {D[mt][ntl][0], D[mt][ntl][1]};
                    float2 v1 = {D[mt][ntl][2], D[mt][ntl][3]};
                    *(float2*)&P[(size_t)row0 * Hv + col] = v0;
                    *(float2*)&P[(size_t)(row0 + 8) * Hv + col] = v1;
                }
            }
        }

        // ---- barrier 1, x[t+1] staging in its shadow ----
        __threadfence();
        __syncthreads();
        if (t + 1 < Tv) {
            const char* xh = (const char*)(g_xh + ((size_t)(t + 1) * Bv + srow) * Iv + xbase) + xsoff;
            const char* xl = (const char*)(g_xl + ((size_t)(t + 1) * Bv + srow) * Iv + xbase) + xsoff;
#pragma unroll
            for (int j = 0; j < 2; j++) {
                uint4 a = __ldcg((const uint4*)xh + j);
                uint4 b = __ldcg((const uint4*)xl + j);
                *(uint4*)(sXhh + rb + ((xsoff + j * 16) ^ sws)) = a;
                *(uint4*)(sXhl + rb + ((xsoff + j * 16) ^ sws)) = b;
            }
        }
        if (tid == 0) {
            unsigned gen = g_bar_gen;
            unsigned prev = atomicAdd(&g_bar_count, 1u);
            if (prev == NBLK_SCAN - 1) { g_bar_count = 0; __threadfence(); g_bar_gen = gen + 1; }
            else { while (g_bar_gen == gen) {} }
        }
        __syncthreads();

        // ---- phase 2: reduce 16 partials + bias + tanh (threads 0..127) ----
        if (tid < 128) {
            float4 s = bb;
#pragma unroll
            for (int c = 0; c < KCHUNKS; c++) {
                float4 p = __ldcg((const float4*)&g_part[c][e]);
                s.x += p.x; s.y += p.y; s.z += p.z; s.w += p.w;
            }
            float h[4] = {tanhf(s.x), tanhf(s.y), tanhf(s.z), tanhf(s.w)};
            unsigned short hh[4], hl[4];
#pragma unroll
            for (int j = 0; j < 4; j++) {
                __nv_bfloat16 a = __float2bfloat16(h[j]);
                __nv_bfloat16 b = __float2bfloat16(h[j] - __bfloat162float(a));
                hh[j] = __bfloat16_as_ushort(a);
                hl[j] = __bfloat16_as_ushort(b);
            }
            *(ull*)&g_hh[e] = *(const ull*)hh;
            *(ull*)&g_hl[e] = *(const ull*)hl;
        }

        // ---- barrier 2 ----
        __threadfence();
        __syncthreads();
        if (tid == 0) {
            unsigned gen = g_bar_gen;
            unsigned prev = atomicAdd(&g_bar_count, 1u);
            if (prev == NBLK_SCAN - 1) { g_bar_count = 0; __threadfence(); g_bar_gen = gen + 1; }
            else { while (g_bar_gen == gen) {} }
        }
        __syncthreads();
    }
}

// ============================================================
// Kernel C: out[b][o] = h_last[b][:] @ fc_w[:, o] + fc_b[o]
// ============================================================
__global__ void __launch_bounds__(256, 1) fc_kernel(
    const float* __restrict__ fcw, const float* __restrict__ fcb,
    float* __restrict__ out)
{
    __shared__ float hs[Hv];
    const int b = blockIdx.x;
    for (int i = threadIdx.x; i < Hv; i += 256) {
        hs[i] = __bfloat162float(g_hh[(size_t)b * Hv + i]) +
                __bfloat162float(g_hl[(size_t)b * Hv + i]);
    }
    __syncthreads();

    const int o = threadIdx.x;
    float a0 = 0.f, a1 = 0.f, a2 = 0.f, a3 = 0.f;
#pragma unroll 4
    for (int k = 0; k < Hv; k += 4) {
        a0 = fmaf(hs[k + 0], fcw[(size_t)(k + 0) * Ov + o], a0);
        a1 = fmaf(hs[k + 1], fcw[(size_t)(k + 1) * Ov + o], a1);
        a2 = fmaf(hs[k + 2], fcw[(size_t)(k + 2) * Ov + o], a2);
        a3 = fmaf(hs[k + 3], fcw[(size_t)(k + 3) * Ov + o], a3);
    }
    out[(size_t)b * Ov + o] = (a0 + a1) + (a2 + a3) + fcb[o];
}

// ============================================================
extern "C" void kernel_launch(void* const* d_in, const int* in_sizes, int n_in,
                              void* d_out, int out_size)
{
    const float* x   = (const float*)d_in[0];
    const float* wk  = (const float*)d_in[1];
    const float* wr  = (const float*)d_in[2];
    const float* bs  = (const float*)d_in[3];
    const float* fcw = (const float*)d_in[4];
    const float* fcb = (const float*)d_in[5];
    float* out = (float*)d_out;

    static int smem_set = 0;
    if (!smem_set) {
        cudaFuncSetAttribute(scan_kernel,
                             cudaFuncAttributeMaxDynamicSharedMemorySize, 98304);
        smem_set = 1;
    }

    size_t nx8 = (size_t)Bv * Tv * Iv / 8;
    split_x<<<(unsigned)((nx8 + 255) / 256), 256>>>(x);
    scan_kernel<<<NBLK_SCAN, 256, 98304>>>(wr, wk, bs);
    fc_kernel<<<Bv, 256>>>(fcw, fcb, out);
}

// round 14
// speedup vs baseline: 1.1960x; 1.1960x over previous
#include <cuda_runtime.h>
#include <cuda_bf16.h>
#include <math.h>
#include <cstdint>

// Problem dims
#define Bv 128
#define Tv 1024
#define Iv 512
#define Hv 1024
#define Ov 256

#define NBLK_SCAN 128   // 16 k-chunks x 8 n-tiles (R10-proven shape)
#define KCHUNKS   16

typedef unsigned long long ull;

// -------- scratch (device globals: no allocation allowed) --------
__device__ __nv_bfloat16 g_xh[(size_t)Tv * Bv * Iv]; // x split hi, [t][b][i]
__device__ __nv_bfloat16 g_xl[(size_t)Tv * Bv * Iv]; // x split lo, [t][b][i]
__device__ __nv_bfloat16 g_hh[Bv * Hv];              // hidden state, bf16 hi
__device__ __nv_bfloat16 g_hl[Bv * Hv];              // hidden state, bf16 lo
__device__ float g_part[KCHUNKS][Bv * Hv];           // split-K partials (8 MB)
__device__ unsigned g_bar_count;
__device__ volatile unsigned g_bar_gen;

// -------- mma.sync / ldmatrix helpers --------
__device__ __forceinline__ uint32_t smem_u32(const void* p) {
    uint32_t a;
    asm("{ .reg .u64 t; cvta.to.shared.u64 t, %1; cvt.u32.u64 %0, t; }"
        : "=r"(a) : "l"(p));
    return a;
}
__device__ __forceinline__ void ldsm4(uint32_t r[4], uint32_t addr) {
    asm volatile("ldmatrix.sync.aligned.m8n8.x4.shared.b16 {%0,%1,%2,%3}, [%4];"
                 : "=r"(r[0]), "=r"(r[1]), "=r"(r[2]), "=r"(r[3]) : "r"(addr));
}
__device__ __forceinline__ void mma_bf16(float d[4], const uint32_t a[4],
                                         const uint32_t b0, const uint32_t b1) {
    asm volatile(
        "mma.sync.aligned.m16n8k16.row.col.f32.bf16.bf16.f32 "
        "{%0,%1,%2,%3}, {%4,%5,%6,%7}, {%8,%9}, {%0,%1,%2,%3};"
        : "+f"(d[0]), "+f"(d[1]), "+f"(d[2]), "+f"(d[3])
        : "r"(a[0]), "r"(a[1]), "r"(a[2]), "r"(a[3]), "r"(b0), "r"(b1));
}
__device__ __forceinline__ uint32_t bf16pack(float a, float b) {
    __nv_bfloat16 x = __float2bfloat16(a);
    __nv_bfloat16 y = __float2bfloat16(b);
    return (uint32_t)__bfloat16_as_ushort(x) |
           ((uint32_t)__bfloat16_as_ushort(y) << 16);
}

// ============================================================
// Kernel 0: split x into bf16 hi/lo, transpose [b][t][i] -> [t][b][i]
// (R10-proven; DRAM-bound ~80%)
// ============================================================
__global__ void __launch_bounds__(256) split_x(const float* __restrict__ X)
{
    size_t idx8 = (size_t)blockIdx.x * 256 + threadIdx.x;
    if (idx8 >= (size_t)Bv * Tv * Iv / 8) return;
    int i = (int)(idx8 & 63) * 8;
    int t = (int)((idx8 >> 6) & 1023);
    int b = (int)(idx8 >> 16);

    const float* src = X + (((size_t)b * Tv + t) * Iv + i);
    float4 f0 = *(const float4*)(src + 0);
    float4 f1 = *(const float4*)(src + 4);
    float f[8] = {f0.x, f0.y, f0.z, f0.w, f1.x, f1.y, f1.z, f1.w};

    uint32_t hi[4], lo[4];
#pragma unroll
    for (int j = 0; j < 4; j++) {
        __nv_bfloat16 h0 = __float2bfloat16(f[2 * j]);
        __nv_bfloat16 h1 = __float2bfloat16(f[2 * j + 1]);
        hi[j] = (uint32_t)__bfloat16_as_ushort(h0) |
                ((uint32_t)__bfloat16_as_ushort(h1) << 16);
        lo[j] = bf16pack(f[2 * j] - __bfloat162float(h0),
                         f[2 * j + 1] - __bfloat162float(h1));
    }
    size_t o = (((size_t)t * Bv + b) * Iv + i);
    *(uint4*)&g_xh[o] = *(const uint4*)hi;
    *(uint4*)&g_xl[o] = *(const uint4*)lo;
}

// ============================================================
// Kernel B: persistent fused scan (R10 shape) with software-pipelined
// x-GEMM: D is pre-initialized with x_t@Wk during the previous step's
// bar1 wait shadow. X tile double-buffered.
// SMEM 160KB: Ahh 16K | Ahl 16K | Bwh 16K | Bwl 16K | Kwh 16K | Kwl 16K |
//             Xhh0 16K | Xhl0 16K | Xhh1 16K | Xhl1 16K
// ============================================================
__global__ void __launch_bounds__(256, 1) scan_kernel(
    const float* __restrict__ WR, const float* __restrict__ WK,
    const float* __restrict__ bias)
{
    extern __shared__ __align__(1024) char smem[];
    char* sAhh = smem;                     // 16384
    char* sAhl = smem + 16384;
    char* sBwh = smem + 32768;
    char* sBwl = smem + 49152;
    char* sKwh = smem + 65536;
    char* sKwl = smem + 81920;
    char* sXhh = smem + 98304;             // buf0 hi; buf stride 32768
    char* sXhl = smem + 114688;            // buf0 lo; buf stride 32768
    const uint32_t pAhh = smem_u32(smem);
    const uint32_t pAhl = pAhh + 16384;
    const uint32_t pBwh = pAhh + 32768;
    const uint32_t pBwl = pAhh + 49152;
    const uint32_t pKwh = pAhh + 65536;
    const uint32_t pKwl = pAhh + 81920;
    const uint32_t pXhh = pAhh + 98304;
    const uint32_t pXhl = pAhh + 114688;

    const int tid = threadIdx.x;
    const int wid = tid >> 5;
    const int lid = tid & 31;
    const int bi = blockIdx.x;
    const int kc = bi >> 3;            // 0..15
    const int nt = bi & 7;             // 0..7
    const int kbase = kc * 64;
    const int xbase = kc * 32;
    const int nbase = nt * 128;
    const int e = (bi * 256 + tid) * 4;

    const int wm = wid & 1;
    const int wn = wid >> 1;

    // ldmatrix lane invariants (R7-proven)
    const int rowA = ((lid >> 3) & 1) * 8 + (lid & 7);
    const int khA  = (lid >> 4) * 16;
    const int rowB = ((lid >> 4) & 1) * 8 + (lid & 7);
    const int khB  = ((lid >> 3) & 1) * 16;
    const int sw   = (lid & 7) << 4;
    const uint32_t aHiBase = pAhh + (wm * 64 + rowA) * 128;
    const uint32_t aLoBase = pAhl + (wm * 64 + rowA) * 128;
    const uint32_t bHiBase = pBwh + (wn * 32 + rowB) * 128;
    const uint32_t bLoBase = pBwl + (wn * 32 + rowB) * 128;
    const uint32_t kHiBase = pKwh + (wn * 32 + rowB) * 128;
    const uint32_t kLoBase = pKwl + (wn * 32 + rowB) * 128;
    const uint32_t xHiBase = pXhh + (wm * 64 + rowA) * 128;   // + buf*32768
    const uint32_t xLoBase = pXhl + (wm * 64 + rowA) * 128;   // + buf*32768

    // ---- preload Wr slice (split hi/lo, [n][k], swizzled) ----
    for (int idx = tid; idx < 128 * 64; idx += 256) {
        int n = idx & 127;
        int k = idx >> 7;
        float w = WR[(size_t)(kbase + k) * Hv + nbase + n];
        __nv_bfloat16 wh = __float2bfloat16(w);
        __nv_bfloat16 wl = __float2bfloat16(w - __bfloat162float(wh));
        uint32_t off = n * 128 + ((k * 2) ^ ((n & 7) << 4));
        *(__nv_bfloat16*)(sBwh + off) = wh;
        *(__nv_bfloat16*)(sBwl + off) = wl;
    }
    // ---- preload Wk slice ----
    for (int idx = tid; idx < 128 * 32; idx += 256) {
        int n = idx & 127;
        int k = idx >> 7;
        float w = WK[(size_t)(xbase + k) * Hv + nbase + n];
        __nv_bfloat16 wh = __float2bfloat16(w);
        __nv_bfloat16 wl = __float2bfloat16(w - __bfloat162float(wh));
        uint32_t off = n * 128 + ((k * 2) ^ ((n & 7) << 4));
        *(__nv_bfloat16*)(sKwh + off) = wh;
        *(__nv_bfloat16*)(sKwl + off) = wl;
    }

    *(ull*)&g_hh[e] = 0ull;
    *(ull*)&g_hl[e] = 0ull;

    float4 bb = *(const float4*)&bias[tid * 4];

    const int srow = tid >> 1;
    const int soff = (tid & 1) * 64;   // h tile: 64B half
    const int xoff = (tid & 1) * 32;   // x tile: 32B half
    const uint32_t rb = srow * 128;
    const uint32_t sws = (srow & 7) << 4;

    // ---- stage x[0] into buf 0 ----
    {
        const char* xh = (const char*)(g_xh + (size_t)srow * Iv + xbase) + xoff;
        const char* xl = (const char*)(g_xl + (size_t)srow * Iv + xbase) + xoff;
#pragma unroll
        for (int j = 0; j < 2; j++) {
            uint4 a = __ldcg((const uint4*)xh + j);
            uint4 b = __ldcg((const uint4*)xl + j);
            *(uint4*)(sXhh + rb + ((xoff + j * 16) ^ sws)) = a;
            *(uint4*)(sXhl + rb + ((xoff + j * 16) ^ sws)) = b;
        }
    }
    __syncthreads();

    // ---- prologue: D = x[0] @ Wk ----
    float D[4][4][4];
#pragma unroll
    for (int i = 0; i < 4; i++)
#pragma unroll
        for (int j = 0; j < 4; j++)
#pragma unroll
            for (int q = 0; q < 4; q++) D[i][j][q] = 0.f;
#pragma unroll
    for (int ks = 0; ks < 2; ks++) {
        const uint32_t koffA = ((ks * 32) | khA) ^ sw;
        const uint32_t koffB = ((ks * 32) | khB) ^ sw;
        uint32_t Ah[4][4], Al[4][4], Bh[2][4], Bl[2][4];
#pragma unroll
        for (int mt = 0; mt < 4; mt++) {
            ldsm4(Ah[mt], xHiBase + mt * 2048 + koffA);
            ldsm4(Al[mt], xLoBase + mt * 2048 + koffA);
        }
#pragma unroll
        for (int np = 0; np < 2; np++) {
            ldsm4(Bh[np], kHiBase + np * 2048 + koffB);
            ldsm4(Bl[np], kLoBase + np * 2048 + koffB);
        }
#pragma unroll
        for (int mt = 0; mt < 4; mt++) {
#pragma unroll
            for (int ntl = 0; ntl < 4; ntl++) {
                const int np = ntl >> 1, q = (ntl & 1) * 2;
                mma_bf16(D[mt][ntl], Ah[mt], Bh[np][q], Bh[np][q + 1]);
                mma_bf16(D[mt][ntl], Al[mt], Bh[np][q], Bh[np][q + 1]);
                mma_bf16(D[mt][ntl], Ah[mt], Bl[np][q], Bl[np][q + 1]);
            }
        }
    }

    // ---- initial grid barrier (R10 flat) ----
    __threadfence();
    __syncthreads();
    if (tid == 0) {
        unsigned gen = g_bar_gen;
        unsigned prev = atomicAdd(&g_bar_count, 1u);
        if (prev == NBLK_SCAN - 1) { g_bar_count = 0; __threadfence(); g_bar_gen = gen + 1; }
        else { while (g_bar_gen == gen) {} }
    }
    __syncthreads();

#pragma unroll 1
    for (int t = 0; t < Tv; t++) {
        // ---- stage h slice (bf16 hi/lo, K-major, swizzled) ----
        {
            const char* sh = (const char*)(g_hh + (size_t)srow * Hv + kbase) + soff;
            const char* sl = (const char*)(g_hl + (size_t)srow * Hv + kbase) + soff;
            uint4 h0 = __ldcg((const uint4*)sh + 0);
            uint4 h1 = __ldcg((const uint4*)sh + 1);
            uint4 h2 = __ldcg((const uint4*)sh + 2);
            uint4 h3 = __ldcg((const uint4*)sh + 3);
            uint4 l0 = __ldcg((const uint4*)sl + 0);
            uint4 l1 = __ldcg((const uint4*)sl + 1);
            uint4 l2 = __ldcg((const uint4*)sl + 2);
            uint4 l3 = __ldcg((const uint4*)sl + 3);
            *(uint4*)(sAhh + rb + ((soff +  0) ^ sws)) = h0;
            *(uint4*)(sAhh + rb + ((soff + 16) ^ sws)) = h1;
            *(uint4*)(sAhh + rb + ((soff + 32) ^ sws)) = h2;
            *(uint4*)(sAhh + rb + ((soff + 48) ^ sws)) = h3;
            *(uint4*)(sAhl + rb + ((soff +  0) ^ sws)) = l0;
            *(uint4*)(sAhl + rb + ((soff + 16) ^ sws)) = l1;
            *(uint4*)(sAhl + rb + ((soff + 32) ^ sws)) = l2;
            *(uint4*)(sAhl + rb + ((soff + 48) ^ sws)) = l3;
        }
        __syncthreads();

        // ---- rec-GEMM: D += h @ Wr (K=64, 4 ks, 3 terms) ----
#pragma unroll
        for (int ks = 0; ks < 4; ks++) {
            const uint32_t koffA = ((ks * 32) | khA) ^ sw;
            const uint32_t koffB = ((ks * 32) | khB) ^ sw;
            uint32_t Ah[4][4], Al[4][4], Bh[2][4], Bl[2][4];
#pragma unroll
            for (int mt = 0; mt < 4; mt++) {
                ldsm4(Ah[mt], aHiBase + mt * 2048 + koffA);
                ldsm4(Al[mt], aLoBase + mt * 2048 + koffA);
            }
#pragma unroll
            for (int np = 0; np < 2; np++) {
                ldsm4(Bh[np], bHiBase + np * 2048 + koffB);
                ldsm4(Bl[np], bLoBase + np * 2048 + koffB);
            }
#pragma unroll
            for (int mt = 0; mt < 4; mt++) {
#pragma unroll
                for (int ntl = 0; ntl < 4; ntl++) {
                    const int np = ntl >> 1, q = (ntl & 1) * 2;
                    mma_bf16(D[mt][ntl], Ah[mt], Bh[np][q], Bh[np][q + 1]);
                    mma_bf16(D[mt][ntl], Al[mt], Bh[np][q], Bh[np][q + 1]);
                    mma_bf16(D[mt][ntl], Ah[mt], Bl[np][q], Bl[np][q + 1]);
                }
            }
        }

        // ---- write split-K partials ----
        {
            const int g = lid >> 2, c2 = (lid & 3) * 2;
            float* P = g_part[kc];
#pragma unroll
            for (int mt = 0; mt < 4; mt++) {
#pragma unroll
                for (int ntl = 0; ntl < 4; ntl++) {
                    int row0 = wm * 64 + mt * 16 + g;
                    int col = nbase + wn * 32 + ntl * 8 + c2;
                    float2 v0 = {D[mt][ntl][0], D[mt][ntl][1]};
                    float2 v1 = {D[mt][ntl][2], D[mt][ntl][3]};
                    *(float2*)&P[(size_t)row0 * Hv + col] = v0;
                    *(float2*)&P[(size_t)(row0 + 8) * Hv + col] = v1;
                }
            }
        }

        // ---- barrier 1: arrive, then do ALL x[t+1] work in the shadow ----
        __threadfence();
        __syncthreads();
        if (tid == 0) {
            unsigned gen = g_bar_gen;
            unsigned prev = atomicAdd(&g_bar_count, 1u);
            if (prev == NBLK_SCAN - 1) { g_bar_count = 0; __threadfence(); g_bar_gen = gen + 1; }
            // waiter spin happens AFTER the shadow work below
            if (prev != NBLK_SCAN - 1) {
                // defer: record gen for later spin via shared slot? simpler:
            }
        }
        // (re-read gen for the post-shadow spin; gen only advances)
        unsigned gen_snapshot = g_bar_gen;

        const uint32_t nbuf = (uint32_t)((t + 1) & 1) * 32768u;
        if (t + 1 < Tv) {
            const char* xh = (const char*)(g_xh + ((size_t)(t + 1) * Bv + srow) * Iv + xbase) + xoff;
            const char* xl = (const char*)(g_xl + ((size_t)(t + 1) * Bv + srow) * Iv + xbase) + xoff;
#pragma unroll
            for (int j = 0; j < 2; j++) {
                uint4 a = __ldcg((const uint4*)xh + j);
                uint4 b = __ldcg((const uint4*)xl + j);
                *(uint4*)(sXhh + nbuf + rb + ((xoff + j * 16) ^ sws)) = a;
                *(uint4*)(sXhl + nbuf + rb + ((xoff + j * 16) ^ sws)) = b;
            }
        }
        __syncthreads();   // sX[nbuf] visible CTA-wide

        // D = x[t+1] @ Wk  (independent of the grid barrier)
#pragma unroll
        for (int i = 0; i < 4; i++)
#pragma unroll
            for (int j = 0; j < 4; j++)
#pragma unroll
                for (int q = 0; q < 4; q++) D[i][j][q] = 0.f;
        if (t + 1 < Tv) {
#pragma unroll
            for (int ks = 0; ks < 2; ks++) {
                const uint32_t koffA = ((ks * 32) | khA) ^ sw;
                const uint32_t koffB = ((ks * 32) | khB) ^ sw;
                uint32_t Ah[4][4], Al[4][4], Bh[2][4], Bl[2][4];
#pragma unroll
                for (int mt = 0; mt < 4; mt++) {
                    ldsm4(Ah[mt], xHiBase + nbuf + mt * 2048 + koffA);
                    ldsm4(Al[mt], xLoBase + nbuf + mt * 2048 + koffA);
                }
#pragma unroll
                for (int np = 0; np < 2; np++) {
                    ldsm4(Bh[np], kHiBase + np * 2048 + koffB);
                    ldsm4(Bl[np], kLoBase + np * 2048 + koffB);
                }
#pragma unroll
                for (int mt = 0; mt < 4; mt++) {
#pragma unroll
                    for (int ntl = 0; ntl < 4; ntl++) {
                        const int np = ntl >> 1, q = (ntl & 1) * 2;
                        mma_bf16(D[mt][ntl], Ah[mt], Bh[np][q], Bh[np][q + 1]);
                        mma_bf16(D[mt][ntl], Al[mt], Bh[np][q], Bh[np][q + 1]);
                        mma_bf16(D[mt][ntl], Ah[mt], Bl[np][q], Bl[np][q + 1]);
                    }
                }
            }
        }

        // now actually wait for the barrier release (often already done)
        if (tid == 0) {
            // release condition: gen advanced past the value seen at OUR arrival.
            // g_bar_gen is monotonic within the launch; our arrival instance's
            // release is gen_arrival+1. gen_snapshot >= gen_arrival, and if the
            // release already happened snapshot is past it. Spin while the count
            // of releases since launch start is behind 1 + 2*t + 1 instances.
            while (g_bar_gen == gen_snapshot && g_bar_count != 0) {}
            // robust spin: wait until all 128 arrivals of this instance consumed
            // (count reset to 0 by releaser) — g_bar_gen flip covers the normal
            // path; the count==0 check covers the snapshot-after-release race.
        }
        __syncthreads();

        // ---- phase 2: reduce partials + bias + tanh -> h (bf16 hi/lo) ----
        {
            float4 s = bb;
#pragma unroll
            for (int c = 0; c < KCHUNKS; c++) {
                float4 p = __ldcg((const float4*)&g_part[c][e]);
                s.x += p.x; s.y += p.y; s.z += p.z; s.w += p.w;
            }
            float h[4] = {tanhf(s.x), tanhf(s.y), tanhf(s.z), tanhf(s.w)};
            unsigned short hh[4], hl[4];
#pragma unroll
            for (int j = 0; j < 4; j++) {
                __nv_bfloat16 a = __float2bfloat16(h[j]);
                __nv_bfloat16 b = __float2bfloat16(h[j] - __bfloat162float(a));
                hh[j] = __bfloat16_as_ushort(a);
                hl[j] = __bfloat16_as_ushort(b);
            }
            *(ull*)&g_hh[e] = *(const ull*)hh;
            *(ull*)&g_hl[e] = *(const ull*)hl;
        }

        // ---- barrier 2 (R10 form) ----
        __threadfence();
        __syncthreads();
        if (tid == 0) {
            unsigned gen = g_bar_gen;
            unsigned prev = atomicAdd(&g_bar_count, 1u);
            if (prev == NBLK_SCAN - 1) { g_bar_count = 0; __threadfence(); g_bar_gen = gen + 1; }
            else { while (g_bar_gen == gen) {} }
        }
        __syncthreads();
    }
}

// ============================================================
// Kernel C: out[b][o] = h_last[b][:] @ fc_w[:, o] + fc_b[o]
// ============================================================
__global__ void __launch_bounds__(256, 1) fc_kernel(
    const float* __restrict__ fcw, const float* __restrict__ fcb,
    float* __restrict__ out)
{
    __shared__ float hs[Hv];
    const int b = blockIdx.x;
    for (int i = threadIdx.x; i < Hv; i += 256) {
        hs[i] = __bfloat162float(g_hh[(size_t)b * Hv + i]) +
                __bfloat162float(g_hl[(size_t)b * Hv + i]);
    }
    __syncthreads();

    const int o = threadIdx.x;
    float a0 = 0.f, a1 = 0.f, a2 = 0.f, a3 = 0.f;
#pragma unroll 4
    for (int k = 0; k < Hv; k += 4) {
        a0 = fmaf(hs[k + 0], fcw[(size_t)(k + 0) * Ov + o], a0);
        a1 = fmaf(hs[k + 1], fcw[(size_t)(k + 1) * Ov + o], a1);
        a2 = fmaf(hs[k + 2], fcw[(size_t)(k + 2) * Ov + o], a2);
        a3 = fmaf(hs[k + 3], fcw[(size_t)(k + 3) * Ov + o], a3);
    }
    out[(size_t)b * Ov + o] = (a0 + a1) + (a2 + a3) + fcb[o];
}

// ============================================================
extern "C" void kernel_launch(void* const* d_in, const int* in_sizes, int n_in,
                              void* d_out, int out_size)
{
    const float* x   = (const float*)d_in[0];
    const float* wk  = (const float*)d_in[1];
    const float* wr  = (const float*)d_in[2];
    const float* bs  = (const float*)d_in[3];
    const float* fcw = (const float*)d_in[4];
    const float* fcb = (const float*)d_in[5];
    float* out = (float*)d_out;

    static int smem_set = 0;
    if (!smem_set) {
        cudaFuncSetAttribute(scan_kernel,
                             cudaFuncAttributeMaxDynamicSharedMemorySize, 163840);
        smem_set = 1;
    }

    size_t nx8 = (size_t)Bv * Tv * Iv / 8;
    split_x<<<(unsigned)((nx8 + 255) / 256), 256>>>(x);
    scan_kernel<<<NBLK_SCAN, 256, 163840>>>(wr, wk, bs);
    fc_kernel<<<Bv, 256>>>(fcw, fcb, out);
}

// round 15
// speedup vs baseline: 1.2501x; 1.0452x over previous
#include <cuda_runtime.h>
#include <cuda_bf16.h>
#include <math.h>
#include <cstdint>

// Problem dims
#define Bv 128
#define Tv 1024
#define Iv 512
#define Hv 1024
#define Ov 256

#define NBLK_SCAN 128   // 16 k-chunks x 8 n-tiles (proven shape)
#define KCHUNKS   16

typedef unsigned long long ull;

// -------- scratch (device globals: no allocation allowed) --------
__device__ __nv_bfloat16 g_xh[(size_t)Tv * Bv * Iv]; // x split hi, [t][b][i]
__device__ __nv_bfloat16 g_xl[(size_t)Tv * Bv * Iv]; // x split lo, [t][b][i]
__device__ __nv_bfloat16 g_hh[Bv * Hv];              // hidden state, bf16 hi
__device__ __nv_bfloat16 g_hl[Bv * Hv];              // hidden state, bf16 lo
__device__ float g_part[KCHUNKS][Bv * Hv];           // split-K partials (8 MB)
__device__ unsigned g_bar_count;                     // monotonic arrivals
__device__ unsigned g_gen;                           // monotonic releases

// -------- monotonic grid barrier (tid0-only; caller wraps in syncthreads) ----
__device__ __forceinline__ void bar_arrive(unsigned gen0, unsigned n) {
    // cumulative fence: CTA's prior stores (ordered to tid0 by __syncthreads)
    // become gpu-visible before the arrival is observed
    asm volatile("fence.acq_rel.gpu;" ::: "memory");
    unsigned prev;
    asm volatile("atom.relaxed.gpu.global.add.u32 %0, [%1], 1;"
                 : "=r"(prev) : "l"(&g_bar_count) : "memory");
    if ((prev & 127u) == 127u) {   // 128th arrival of instance n
        asm volatile("st.release.gpu.u32 [%0], %1;"
                     :: "l"(&g_gen), "r"(gen0 + n) : "memory");
    }
}
__device__ __forceinline__ void bar_wait(unsigned gen0, unsigned n) {
    unsigned cur;
    do {
        asm volatile("ld.acquire.gpu.u32 %0, [%1];"
                     : "=r"(cur) : "l"(&g_gen) : "memory");
    } while ((cur - gen0) < n);
}

// -------- mma.sync / ldmatrix helpers --------
__device__ __forceinline__ uint32_t smem_u32(const void* p) {
    uint32_t a;
    asm("{ .reg .u64 t; cvta.to.shared.u64 t, %1; cvt.u32.u64 %0, t; }"
        : "=r"(a) : "l"(p));
    return a;
}
__device__ __forceinline__ void ldsm4(uint32_t r[4], uint32_t addr) {
    asm volatile("ldmatrix.sync.aligned.m8n8.x4.shared.b16 {%0,%1,%2,%3}, [%4];"
                 : "=r"(r[0]), "=r"(r[1]), "=r"(r[2]), "=r"(r[3]) : "r"(addr));
}
__device__ __forceinline__ void mma_bf16(float d[4], const uint32_t a[4],
                                         const uint32_t b0, const uint32_t b1) {
    asm volatile(
        "mma.sync.aligned.m16n8k16.row.col.f32.bf16.bf16.f32 "
        "{%0,%1,%2,%3}, {%4,%5,%6,%7}, {%8,%9}, {%0,%1,%2,%3};"
        : "+f"(d[0]), "+f"(d[1]), "+f"(d[2]), "+f"(d[3])
        : "r"(a[0]), "r"(a[1]), "r"(a[2]), "r"(a[3]), "r"(b0), "r"(b1));
}
__device__ __forceinline__ uint32_t bf16pack(float a, float b) {
    __nv_bfloat16 x = __float2bfloat16(a);
    __nv_bfloat16 y = __float2bfloat16(b);
    return (uint32_t)__bfloat16_as_ushort(x) |
           ((uint32_t)__bfloat16_as_ushort(y) << 16);
}

// ============================================================
// Kernel 0: split x into bf16 hi/lo, transpose [b][t][i] -> [t][b][i]
// ============================================================
__global__ void __launch_bounds__(256) split_x(const float* __restrict__ X)
{
    size_t idx8 = (size_t)blockIdx.x * 256 + threadIdx.x;
    if (idx8 >= (size_t)Bv * Tv * Iv / 8) return;
    int i = (int)(idx8 & 63) * 8;
    int t = (int)((idx8 >> 6) & 1023);
    int b = (int)(idx8 >> 16);

    const float* src = X + (((size_t)b * Tv + t) * Iv + i);
    float4 f0 = *(const float4*)(src + 0);
    float4 f1 = *(const float4*)(src + 4);
    float f[8] = {f0.x, f0.y, f0.z, f0.w, f1.x, f1.y, f1.z, f1.w};

    uint32_t hi[4], lo[4];
#pragma unroll
    for (int j = 0; j < 4; j++) {
        __nv_bfloat16 h0 = __float2bfloat16(f[2 * j]);
        __nv_bfloat16 h1 = __float2bfloat16(f[2 * j + 1]);
        hi[j] = (uint32_t)__bfloat16_as_ushort(h0) |
                ((uint32_t)__bfloat16_as_ushort(h1) << 16);
        lo[j] = bf16pack(f[2 * j] - __bfloat162float(h0),
                         f[2 * j + 1] - __bfloat162float(h1));
    }
    size_t o = (((size_t)t * Bv + b) * Iv + i);
    *(uint4*)&g_xh[o] = *(const uint4*)hi;
    *(uint4*)&g_xl[o] = *(const uint4*)lo;
}

// ============================================================
// Kernel B: persistent fused scan (R14 structure, hardened barrier).
// x-GEMM pipelined into bar1's wait shadow; X tile double-buffered.
// SMEM 160KB: Ahh|Ahl 32K, Bwh|Bwl 32K, Kwh|Kwl 32K, X bufs 64K
// ============================================================
__global__ void __launch_bounds__(256, 1) scan_kernel(
    const float* __restrict__ WR, const float* __restrict__ WK,
    const float* __restrict__ bias)
{
    extern __shared__ __align__(1024) char smem[];
    char* sAhh = smem;
    char* sAhl = smem + 16384;
    char* sBwh = smem + 32768;
    char* sBwl = smem + 49152;
    char* sKwh = smem + 65536;
    char* sKwl = smem + 81920;
    char* sXhh = smem + 98304;             // buf0 hi; buf stride 32768
    char* sXhl = smem + 114688;            // buf0 lo; buf stride 32768
    const uint32_t pAhh = smem_u32(smem);
    const uint32_t pAhl = pAhh + 16384;
    const uint32_t pBwh = pAhh + 32768;
    const uint32_t pBwl = pAhh + 49152;
    const uint32_t pKwh = pAhh + 65536;
    const uint32_t pKwl = pAhh + 81920;
    const uint32_t pXhh = pAhh + 98304;
    const uint32_t pXhl = pAhh + 114688;

    const int tid = threadIdx.x;
    const int wid = tid >> 5;
    const int lid = tid & 31;
    const int bi = blockIdx.x;
    const int kc = bi >> 3;
    const int nt = bi & 7;
    const int kbase = kc * 64;
    const int xbase = kc * 32;
    const int nbase = nt * 128;
    const int e = (bi * 256 + tid) * 4;

    const int wm = wid & 1;
    const int wn = wid >> 1;

    const int rowA = ((lid >> 3) & 1) * 8 + (lid & 7);
    const int khA  = (lid >> 4) * 16;
    const int rowB = ((lid >> 4) & 1) * 8 + (lid & 7);
    const int khB  = ((lid >> 3) & 1) * 16;
    const int sw   = (lid & 7) << 4;
    const uint32_t aHiBase = pAhh + (wm * 64 + rowA) * 128;
    const uint32_t aLoBase = pAhl + (wm * 64 + rowA) * 128;
    const uint32_t bHiBase = pBwh + (wn * 32 + rowB) * 128;
    const uint32_t bLoBase = pBwl + (wn * 32 + rowB) * 128;
    const uint32_t kHiBase = pKwh + (wn * 32 + rowB) * 128;
    const uint32_t kLoBase = pKwl + (wn * 32 + rowB) * 128;
    const uint32_t xHiBase = pXhh + (wm * 64 + rowA) * 128;   // + buf*32768
    const uint32_t xLoBase = pXhl + (wm * 64 + rowA) * 128;   // + buf*32768

    // barrier baseline (pre-first-arrival; all CTAs agree since release #1
    // requires every CTA's arrival)
    unsigned gen0 = 0;
    if (tid == 0) {
        asm volatile("ld.relaxed.gpu.u32 %0, [%1];" : "=r"(gen0) : "l"(&g_gen));
    }

    // ---- preload Wr slice (split hi/lo, [n][k], swizzled) ----
    for (int idx = tid; idx < 128 * 64; idx += 256) {
        int n = idx & 127;
        int k = idx >> 7;
        float w = WR[(size_t)(kbase + k) * Hv + nbase + n];
        __nv_bfloat16 wh = __float2bfloat16(w);
        __nv_bfloat16 wl = __float2bfloat16(w - __bfloat162float(wh));
        uint32_t off = n * 128 + ((k * 2) ^ ((n & 7) << 4));
        *(__nv_bfloat16*)(sBwh + off) = wh;
        *(__nv_bfloat16*)(sBwl + off) = wl;
    }
    // ---- preload Wk slice ----
    for (int idx = tid; idx < 128 * 32; idx += 256) {
        int n = idx & 127;
        int k = idx >> 7;
        float w = WK[(size_t)(xbase + k) * Hv + nbase + n];
        __nv_bfloat16 wh = __float2bfloat16(w);
        __nv_bfloat16 wl = __float2bfloat16(w - __bfloat162float(wh));
        uint32_t off = n * 128 + ((k * 2) ^ ((n & 7) << 4));
        *(__nv_bfloat16*)(sKwh + off) = wh;
        *(__nv_bfloat16*)(sKwl + off) = wl;
    }

    *(ull*)&g_hh[e] = 0ull;
    *(ull*)&g_hl[e] = 0ull;

    float4 bb = *(const float4*)&bias[tid * 4];

    const int srow = tid >> 1;
    const int soff = (tid & 1) * 64;   // h tile: 64B half
    const int xoff = (tid & 1) * 32;   // x tile: 32B half
    const uint32_t rb = srow * 128;
    const uint32_t sws = (srow & 7) << 4;

    // ---- stage x[0] into buf 0 ----
    {
        const char* xh = (const char*)(g_xh + (size_t)srow * Iv + xbase) + xoff;
        const char* xl = (const char*)(g_xl + (size_t)srow * Iv + xbase) + xoff;
#pragma unroll
        for (int j = 0; j < 2; j++) {
            uint4 a = __ldcg((const uint4*)xh + j);
            uint4 b = __ldcg((const uint4*)xl + j);
            *(uint4*)(sXhh + rb + ((xoff + j * 16) ^ sws)) = a;
            *(uint4*)(sXhl + rb + ((xoff + j * 16) ^ sws)) = b;
        }
    }
    __syncthreads();

    // ---- prologue: D = x[0] @ Wk ----
    float D[4][4][4];
#pragma unroll
    for (int i = 0; i < 4; i++)
#pragma unroll
        for (int j = 0; j < 4; j++)
#pragma unroll
            for (int q = 0; q < 4; q++) D[i][j][q] = 0.f;
#pragma unroll
    for (int ks = 0; ks < 2; ks++) {
        const uint32_t koffA = ((ks * 32) | khA) ^ sw;
        const uint32_t koffB = ((ks * 32) | khB) ^ sw;
        uint32_t Ah[4][4], Al[4][4], Bh[2][4], Bl[2][4];
#pragma unroll
        for (int mt = 0; mt < 4; mt++) {
            ldsm4(Ah[mt], xHiBase + mt * 2048 + koffA);
            ldsm4(Al[mt], xLoBase + mt * 2048 + koffA);
        }
#pragma unroll
        for (int np = 0; np < 2; np++) {
            ldsm4(Bh[np], kHiBase + np * 2048 + koffB);
            ldsm4(Bl[np], kLoBase + np * 2048 + koffB);
        }
#pragma unroll
        for (int mt = 0; mt < 4; mt++) {
#pragma unroll
            for (int ntl = 0; ntl < 4; ntl++) {
                const int np = ntl >> 1, q = (ntl & 1) * 2;
                mma_bf16(D[mt][ntl], Ah[mt], Bh[np][q], Bh[np][q + 1]);
                mma_bf16(D[mt][ntl], Al[mt], Bh[np][q], Bh[np][q + 1]);
                mma_bf16(D[mt][ntl], Ah[mt], Bl[np][q], Bl[np][q + 1]);
            }
        }
    }

    // ---- initial barrier (instance 1) ----
    __syncthreads();
    if (tid == 0) { bar_arrive(gen0, 1u); bar_wait(gen0, 1u); }
    __syncthreads();

#pragma unroll 1
    for (int t = 0; t < Tv; t++) {
        const unsigned n1 = 2u + 2u * (unsigned)t;
        const unsigned n2 = 3u + 2u * (unsigned)t;

        // ---- stage h slice (bf16 hi/lo, K-major, swizzled) ----
        {
            const char* sh = (const char*)(g_hh + (size_t)srow * Hv + kbase) + soff;
            const char* sl = (const char*)(g_hl + (size_t)srow * Hv + kbase) + soff;
            uint4 h0 = __ldcg((const uint4*)sh + 0);
            uint4 h1 = __ldcg((const uint4*)sh + 1);
            uint4 h2 = __ldcg((const uint4*)sh + 2);
            uint4 h3 = __ldcg((const uint4*)sh + 3);
            uint4 l0 = __ldcg((const uint4*)sl + 0);
            uint4 l1 = __ldcg((const uint4*)sl + 1);
            uint4 l2 = __ldcg((const uint4*)sl + 2);
            uint4 l3 = __ldcg((const uint4*)sl + 3);
            *(uint4*)(sAhh + rb + ((soff +  0) ^ sws)) = h0;
            *(uint4*)(sAhh + rb + ((soff + 16) ^ sws)) = h1;
            *(uint4*)(sAhh + rb + ((soff + 32) ^ sws)) = h2;
            *(uint4*)(sAhh + rb + ((soff + 48) ^ sws)) = h3;
            *(uint4*)(sAhl + rb + ((soff +  0) ^ sws)) = l0;
            *(uint4*)(sAhl + rb + ((soff + 16) ^ sws)) = l1;
            *(uint4*)(sAhl + rb + ((soff + 32) ^ sws)) = l2;
            *(uint4*)(sAhl + rb + ((soff + 48) ^ sws)) = l3;
        }
        __syncthreads();

        // ---- rec-GEMM: D += h @ Wr (K=64, 4 ks, 3 terms) ----
#pragma unroll
        for (int ks = 0; ks < 4; ks++) {
            const uint32_t koffA = ((ks * 32) | khA) ^ sw;
            const uint32_t koffB = ((ks * 32) | khB) ^ sw;
            uint32_t Ah[4][4], Al[4][4], Bh[2][4], Bl[2][4];
#pragma unroll
            for (int mt = 0; mt < 4; mt++) {
                ldsm4(Ah[mt], aHiBase + mt * 2048 + koffA);
                ldsm4(Al[mt], aLoBase + mt * 2048 + koffA);
            }
#pragma unroll
            for (int np = 0; np < 2; np++) {
                ldsm4(Bh[np], bHiBase + np * 2048 + koffB);
                ldsm4(Bl[np], bLoBase + np * 2048 + koffB);
            }
#pragma unroll
            for (int mt = 0; mt < 4; mt++) {
#pragma unroll
                for (int ntl = 0; ntl < 4; ntl++) {
                    const int np = ntl >> 1, q = (ntl & 1) * 2;
                    mma_bf16(D[mt][ntl], Ah[mt], Bh[np][q], Bh[np][q + 1]);
                    mma_bf16(D[mt][ntl], Al[mt], Bh[np][q], Bh[np][q + 1]);
                    mma_bf16(D[mt][ntl], Ah[mt], Bl[np][q], Bl[np][q + 1]);
                }
            }
        }

        // ---- write split-K partials ----
        {
            const int g = lid >> 2, c2 = (lid & 3) * 2;
            float* P = g_part[kc];
#pragma unroll
            for (int mt = 0; mt < 4; mt++) {
#pragma unroll
                for (int ntl = 0; ntl < 4; ntl++) {
                    int row0 = wm * 64 + mt * 16 + g;
                    int col = nbase + wn * 32 + ntl * 8 + c2;
                    float2 v0 = {D[mt][ntl][0], D[mt][ntl][1]};
                    float2 v1 = {D[mt][ntl][2], D[mt][ntl][3]};
                    *(float2*)&P[(size_t)row0 * Hv + col] = v0;
                    *(float2*)&P[(size_t)(row0 + 8) * Hv + col] = v1;
                }
            }
        }

        // ---- barrier 1: arrive early, x[t+1] work in the wait shadow ----
        __syncthreads();                     // partial stores done CTA-wide
        if (tid == 0) bar_arrive(gen0, n1);

        const uint32_t nbuf = (uint32_t)((t + 1) & 1) * 32768u;
        if (t + 1 < Tv) {
            const char* xh = (const char*)(g_xh + ((size_t)(t + 1) * Bv + srow) * Iv + xbase) + xoff;
            const char* xl = (const char*)(g_xl + ((size_t)(t + 1) * Bv + srow) * Iv + xbase) + xoff;
#pragma unroll
            for (int j = 0; j < 2; j++) {
                uint4 a = __ldcg((const uint4*)xh + j);
                uint4 b = __ldcg((const uint4*)xl + j);
                *(uint4*)(sXhh + nbuf + rb + ((xoff + j * 16) ^ sws)) = a;
                *(uint4*)(sXhl + nbuf + rb + ((xoff + j * 16) ^ sws)) = b;
            }
        }
        __syncthreads();   // sX[nbuf] visible CTA-wide

        // D = x[t+1] @ Wk  (independent of the grid barrier)
#pragma unroll
        for (int i = 0; i < 4; i++)
#pragma unroll
            for (int j = 0; j < 4; j++)
#pragma unroll
                for (int q = 0; q < 4; q++) D[i][j][q] = 0.f;
        if (t + 1 < Tv) {
#pragma unroll
            for (int ks = 0; ks < 2; ks++) {
                const uint32_t koffA = ((ks * 32) | khA) ^ sw;
                const uint32_t koffB = ((ks * 32) | khB) ^ sw;
                uint32_t Ah[4][4], Al[4][4], Bh[2][4], Bl[2][4];
#pragma unroll
                for (int mt = 0; mt < 4; mt++) {
                    ldsm4(Ah[mt], xHiBase + nbuf + mt * 2048 + koffA);
                    ldsm4(Al[mt], xLoBase + nbuf + mt * 2048 + koffA);
                }
#pragma unroll
                for (int np = 0; np < 2; np++) {
                    ldsm4(Bh[np], kHiBase + np * 2048 + koffB);
                    ldsm4(Bl[np], kLoBase + np * 2048 + koffB);
                }
#pragma unroll
                for (int mt = 0; mt < 4; mt++) {
#pragma unroll
                    for (int ntl = 0; ntl < 4; ntl++) {
                        const int np = ntl >> 1, q = (ntl & 1) * 2;
                        mma_bf16(D[mt][ntl], Ah[mt], Bh[np][q], Bh[np][q + 1]);
                        mma_bf16(D[mt][ntl], Al[mt], Bh[np][q], Bh[np][q + 1]);
                        mma_bf16(D[mt][ntl], Ah[mt], Bl[np][q], Bl[np][q + 1]);
                    }
                }
            }
        }

        // deferred wait (provably correct: monotonic instance count)
        if (tid == 0) bar_wait(gen0, n1);
        __syncthreads();

        // ---- phase 2: reduce partials + bias + tanh -> h (bf16 hi/lo) ----
        {
            float4 s = bb;
#pragma unroll
            for (int c = 0; c < KCHUNKS; c++) {
                float4 p = __ldcg((const float4*)&g_part[c][e]);
                s.x += p.x; s.y += p.y; s.z += p.z; s.w += p.w;
            }
            float h[4] = {tanhf(s.x), tanhf(s.y), tanhf(s.z), tanhf(s.w)};
            unsigned short hh[4], hl[4];
#pragma unroll
            for (int j = 0; j < 4; j++) {
                __nv_bfloat16 a = __float2bfloat16(h[j]);
                __nv_bfloat16 b = __float2bfloat16(h[j] - __bfloat162float(a));
                hh[j] = __bfloat16_as_ushort(a);
                hl[j] = __bfloat16_as_ushort(b);
            }
            *(ull*)&g_hh[e] = *(const ull*)hh;
            *(ull*)&g_hl[e] = *(const ull*)hl;
        }

        // ---- barrier 2 ----
        __syncthreads();
        if (tid == 0) { bar_arrive(gen0, n2); bar_wait(gen0, n2); }
        __syncthreads();
    }
}

// ============================================================
// Kernel C: out[b][o] = h_last[b][:] @ fc_w[:, o] + fc_b[o]
// ============================================================
__global__ void __launch_bounds__(256, 1) fc_kernel(
    const float* __restrict__ fcw, const float* __restrict__ fcb,
    float* __restrict__ out)
{
    __shared__ float hs[Hv];
    const int b = blockIdx.x;
    for (int i = threadIdx.x; i < Hv; i += 256) {
        hs[i] = __bfloat162float(g_hh[(size_t)b * Hv + i]) +
                __bfloat162float(g_hl[(size_t)b * Hv + i]);
    }
    __syncthreads();

    const int o = threadIdx.x;
    float a0 = 0.f, a1 = 0.f, a2 = 0.f, a3 = 0.f;
#pragma unroll 4
    for (int k = 0; k < Hv; k += 4) {
        a0 = fmaf(hs[k + 0], fcw[(size_t)(k + 0) * Ov + o], a0);
        a1 = fmaf(hs[k + 1], fcw[(size_t)(k + 1) * Ov + o], a1);
        a2 = fmaf(hs[k + 2], fcw[(size_t)(k + 2) * Ov + o], a2);
        a3 = fmaf(hs[k + 3], fcw[(size_t)(k + 3) * Ov + o], a3);
    }
    out[(size_t)b * Ov + o] = (a0 + a1) + (a2 + a3) + fcb[o];
}

// ============================================================
extern "C" void kernel_launch(void* const* d_in, const int* in_sizes, int n_in,
                              void* d_out, int out_size)
{
    const float* x   = (const float*)d_in[0];
    const float* wk  = (const float*)d_in[1];
    const float* wr  = (const float*)d_in[2];
    const float* bs  = (const float*)d_in[3];
    const float* fcw = (const float*)d_in[4];
    const float* fcb = (const float*)d_in[5];
    float* out = (float*)d_out;

    static int smem_set = 0;
    if (!smem_set) {
        cudaFuncSetAttribute(scan_kernel,
                             cudaFuncAttributeMaxDynamicSharedMemorySize, 163840);
        smem_set = 1;
    }

    size_t nx8 = (size_t)Bv * Tv * Iv / 8;
    split_x<<<(unsigned)((nx8 + 255) / 256), 256>>>(x);
    scan_kernel<<<NBLK_SCAN, 256, 163840>>>(wr, wk, bs);
    fc_kernel<<<Bv, 256>>>(fcw, fcb, out);
}

// round 16
// speedup vs baseline: 1.3420x; 1.0735x over previous
#include <cuda_runtime.h>
#include <cuda_bf16.h>
#include <math.h>
#include <cstdint>

// Problem dims
#define Bv 128
#define Tv 1024
#define Iv 512
#define Hv 1024
#define Ov 256

#define NBLK_SCAN 128   // 2 domains x 64 CTAs (kc16 x nt4 each)
#define KCHUNKS   16
#define DOM_CTAS  64

typedef unsigned long long ull;

// -------- scratch (device globals: no allocation allowed) --------
__device__ __nv_bfloat16 g_xh[(size_t)Tv * Bv * Iv]; // x split hi, [t][b][i]
__device__ __nv_bfloat16 g_xl[(size_t)Tv * Bv * Iv]; // x split lo, [t][b][i]
__device__ __nv_bfloat16 g_hh[Bv * Hv];              // hidden state, bf16 hi
__device__ __nv_bfloat16 g_hl[Bv * Hv];              // hidden state, bf16 lo
__device__ float g_part[KCHUNKS][Bv * Hv];           // split-K partials (8 MB)
__device__ unsigned g_cnt2[2 * 32];                  // per-domain arrival counters
__device__ unsigned g_gen2[2 * 32];                  // per-domain release words

// -------- per-domain monotonic barrier (tid0-only) --------
__device__ __forceinline__ void bar_arrive(int d, unsigned gen0, unsigned n) {
    asm volatile("fence.acq_rel.gpu;" ::: "memory");
    unsigned prev;
    asm volatile("atom.relaxed.gpu.global.add.u32 %0, [%1], 1;"
                 : "=r"(prev) : "l"(&g_cnt2[d * 32]) : "memory");
    if ((prev & 63u) == 63u) {   // 64th arrival of instance n in this domain
        asm volatile("st.release.gpu.u32 [%0], %1;"
                     :: "l"(&g_gen2[d * 32]), "r"(gen0 + n) : "memory");
    }
}
__device__ __forceinline__ void bar_wait(int d, unsigned gen0, unsigned n) {
    unsigned cur;
    do {
        asm volatile("ld.acquire.gpu.u32 %0, [%1];"
                     : "=r"(cur) : "l"(&g_gen2[d * 32]) : "memory");
    } while ((cur - gen0) < n);
}

// -------- mma.sync / ldmatrix helpers --------
__device__ __forceinline__ uint32_t smem_u32(const void* p) {
    uint32_t a;
    asm("{ .reg .u64 t; cvta.to.shared.u64 t, %1; cvt.u32.u64 %0, t; }"
        : "=r"(a) : "l"(p));
    return a;
}
__device__ __forceinline__ void ldsm4(uint32_t r[4], uint32_t addr) {
    asm volatile("ldmatrix.sync.aligned.m8n8.x4.shared.b16 {%0,%1,%2,%3}, [%4];"
                 : "=r"(r[0]), "=r"(r[1]), "=r"(r[2]), "=r"(r[3]) : "r"(addr));
}
__device__ __forceinline__ void mma_bf16(float d[4], const uint32_t a[4],
                                         const uint32_t b0, const uint32_t b1) {
    asm volatile(
        "mma.sync.aligned.m16n8k16.row.col.f32.bf16.bf16.f32 "
        "{%0,%1,%2,%3}, {%4,%5,%6,%7}, {%8,%9}, {%0,%1,%2,%3};"
        : "+f"(d[0]), "+f"(d[1]), "+f"(d[2]), "+f"(d[3])
        : "r"(a[0]), "r"(a[1]), "r"(a[2]), "r"(a[3]), "r"(b0), "r"(b1));
}
__device__ __forceinline__ uint32_t bf16pack(float a, float b) {
    __nv_bfloat16 x = __float2bfloat16(a);
    __nv_bfloat16 y = __float2bfloat16(b);
    return (uint32_t)__bfloat16_as_ushort(x) |
           ((uint32_t)__bfloat16_as_ushort(y) << 16);
}

// ============================================================
// Kernel 0: split x into bf16 hi/lo, transpose [b][t][i] -> [t][b][i]
// ============================================================
__global__ void __launch_bounds__(256) split_x(const float* __restrict__ X)
{
    size_t idx8 = (size_t)blockIdx.x * 256 + threadIdx.x;
    if (idx8 >= (size_t)Bv * Tv * Iv / 8) return;
    int i = (int)(idx8 & 63) * 8;
    int t = (int)((idx8 >> 6) & 1023);
    int b = (int)(idx8 >> 16);

    const float* src = X + (((size_t)b * Tv + t) * Iv + i);
    float4 f0 = *(const float4*)(src + 0);
    float4 f1 = *(const float4*)(src + 4);
    float f[8] = {f0.x, f0.y, f0.z, f0.w, f1.x, f1.y, f1.z, f1.w};

    uint32_t hi[4], lo[4];
#pragma unroll
    for (int j = 0; j < 4; j++) {
        __nv_bfloat16 h0 = __float2bfloat16(f[2 * j]);
        __nv_bfloat16 h1 = __float2bfloat16(f[2 * j + 1]);
        hi[j] = (uint32_t)__bfloat16_as_ushort(h0) |
                ((uint32_t)__bfloat16_as_ushort(h1) << 16);
        lo[j] = bf16pack(f[2 * j] - __bfloat162float(h0),
                         f[2 * j + 1] - __bfloat162float(h1));
    }
    size_t o = (((size_t)t * Bv + b) * Iv + i);
    *(uint4*)&g_xh[o] = *(const uint4*)hi;
    *(uint4*)&g_xl[o] = *(const uint4*)lo;
}

// ============================================================
// Kernel B: persistent fused scan, 2 independent batch domains.
// Domain d (64 batch rows): 64 CTAs (kc16 x nt4), CTA tile 64M x 256N,
// rec K=64 + x K=32, 3-term bf16 split, x-GEMM in bar1's wait shadow.
// SMEM 176KB: Ahh 8K|Ahl 8K | Bwh 32K|Bwl 32K | Kwh 32K|Kwl 32K |
//             Xhh0/1 8K ea | Xhl0/1 8K ea (buf stride 16384 inside arrays)
// ============================================================
__global__ void __launch_bounds__(256, 1) scan_kernel(
    const float* __restrict__ WR, const float* __restrict__ WK,
    const float* __restrict__ bias)
{
    extern __shared__ __align__(1024) char smem[];
    char* sAhh = smem;                     // 8192
    char* sAhl = smem + 8192;              // 8192
    char* sBwh = smem + 16384;             // 32768
    char* sBwl = smem + 49152;             // 32768
    char* sKwh = smem + 81920;             // 32768
    char* sKwl = smem + 114688;            // 32768
    char* sXhh = smem + 147456;            // 2 bufs x 8192
    char* sXhl = smem + 163840;            // 2 bufs x 8192
    const uint32_t pAhh = smem_u32(smem);
    const uint32_t pAhl = pAhh + 8192;
    const uint32_t pBwh = pAhh + 16384;
    const uint32_t pBwl = pAhh + 49152;
    const uint32_t pKwh = pAhh + 81920;
    const uint32_t pKwl = pAhh + 114688;
    const uint32_t pXhh = pAhh + 147456;
    const uint32_t pXhl = pAhh + 163840;

    const int tid = threadIdx.x;
    const int wid = tid >> 5;
    const int lid = tid & 31;
    const int bi = blockIdx.x;
    const int d  = bi >> 6;            // domain 0/1
    const int ib = bi & 63;            // CTA within domain
    const int kc = ib >> 2;            // 0..15
    const int nt = ib & 3;             // 0..3
    const int kbase = kc * 64;         // Wr K slice
    const int xbase = kc * 32;         // Wk K slice
    const int nbase = nt * 256;        // N base (256 cols/CTA)
    const int mrow0 = d * 64;          // global batch-row base
    // reduce ownership: CTA owns global h row (d*64 + ib), cols tid*4..+4
    const size_t e = (size_t)(mrow0 + ib) * Hv + tid * 4;

    const int wm = wid & 1;            // M: 2 warps x 32
    const int wn = wid >> 1;           // N: 4 warps x 64

    // ldmatrix lane invariants (R7-proven mapping)
    const int rowA = ((lid >> 3) & 1) * 8 + (lid & 7);
    const int khA  = (lid >> 4) * 16;
    const int rowB = ((lid >> 4) & 1) * 8 + (lid & 7);
    const int khB  = ((lid >> 3) & 1) * 16;
    const int sw   = (lid & 7) << 4;
    const uint32_t aHiBase = pAhh + (wm * 32 + rowA) * 128;
    const uint32_t aLoBase = pAhl + (wm * 32 + rowA) * 128;
    const uint32_t bHiBase = pBwh + (wn * 64 + rowB) * 128;
    const uint32_t bLoBase = pBwl + (wn * 64 + rowB) * 128;
    const uint32_t kHiBase = pKwh + (wn * 64 + rowB) * 128;
    const uint32_t kLoBase = pKwl + (wn * 64 + rowB) * 128;
    const uint32_t xHiBase = pXhh + (wm * 32 + rowA) * 128;   // + buf*8192
    const uint32_t xLoBase = pXhl + (wm * 32 + rowA) * 128;   // + buf*8192

    // domain barrier baseline
    unsigned gen0 = 0;
    if (tid == 0) {
        asm volatile("ld.relaxed.gpu.u32 %0, [%1];"
                     : "=r"(gen0) : "l"(&g_gen2[d * 32]));
    }

    // ---- preload Wr slice: [n 0..255][k 0..63], swizzled ----
    for (int idx = tid; idx < 256 * 64; idx += 256) {
        int n = idx & 255;
        int k = idx >> 8;
        float w = WR[(size_t)(kbase + k) * Hv + nbase + n];
        __nv_bfloat16 wh = __float2bfloat16(w);
        __nv_bfloat16 wl = __float2bfloat16(w - __bfloat162float(wh));
        uint32_t off = n * 128 + ((k * 2) ^ ((n & 7) << 4));
        *(__nv_bfloat16*)(sBwh + off) = wh;
        *(__nv_bfloat16*)(sBwl + off) = wl;
    }
    // ---- preload Wk slice: [n 0..255][k 0..31], padded 128B rows ----
    for (int idx = tid; idx < 256 * 32; idx += 256) {
        int n = idx & 255;
        int k = idx >> 8;
        float w = WK[(size_t)(xbase + k) * Hv + nbase + n];
        __nv_bfloat16 wh = __float2bfloat16(w);
        __nv_bfloat16 wl = __float2bfloat16(w - __bfloat162float(wh));
        uint32_t off = n * 128 + ((k * 2) ^ ((n & 7) << 4));
        *(__nv_bfloat16*)(sKwh + off) = wh;
        *(__nv_bfloat16*)(sKwl + off) = wl;
    }

    // zero initial hidden state (this CTA's row)
    *(ull*)&g_hh[e] = 0ull;
    *(ull*)&g_hl[e] = 0ull;

    float4 bb = *(const float4*)&bias[tid * 4];

    // staging geometry: 64 rows, 4 threads/row
    const int srow = tid >> 2;             // 0..63
    const int squad = tid & 3;             // 0..3
    const uint32_t rb = srow * 128;
    const uint32_t sws = (srow & 7) << 4;
    const uint32_t soff = squad * 32;      // h tile: 32B quarter of 128B
    const uint32_t xoff = squad * 16;      // x tile: 16B quarter of 64B used

    // ---- stage x[0] into buf 0 ----
    {
        const char* xh = (const char*)(g_xh + (size_t)(mrow0 + srow) * Iv + xbase) + xoff;
        const char* xl = (const char*)(g_xl + (size_t)(mrow0 + srow) * Iv + xbase) + xoff;
        uint4 a = __ldcg((const uint4*)xh);
        uint4 b = __ldcg((const uint4*)xl);
        *(uint4*)(sXhh + rb + (xoff ^ sws)) = a;
        *(uint4*)(sXhl + rb + (xoff ^ sws)) = b;
    }
    __syncthreads();

    // ---- prologue: D = x[0] @ Wk ----
    float D[2][8][4];
#pragma unroll
    for (int i = 0; i < 2; i++)
#pragma unroll
        for (int j = 0; j < 8; j++)
#pragma unroll
            for (int q = 0; q < 4; q++) D[i][j][q] = 0.f;
#pragma unroll
    for (int ks = 0; ks < 2; ks++) {
        const uint32_t koffA = ((ks * 32) | khA) ^ sw;
        const uint32_t koffB = ((ks * 32) | khB) ^ sw;
        uint32_t Ah[2][4], Al[2][4], Bh[4][4], Bl[4][4];
#pragma unroll
        for (int mt = 0; mt < 2; mt++) {
            ldsm4(Ah[mt], xHiBase + mt * 2048 + koffA);
            ldsm4(Al[mt], xLoBase + mt * 2048 + koffA);
        }
#pragma unroll
        for (int np = 0; np < 4; np++) {
            ldsm4(Bh[np], kHiBase + np * 2048 + koffB);
            ldsm4(Bl[np], kLoBase + np * 2048 + koffB);
        }
#pragma unroll
        for (int mt = 0; mt < 2; mt++) {
#pragma unroll
            for (int ntl = 0; ntl < 8; ntl++) {
                const int np = ntl >> 1, q = (ntl & 1) * 2;
                mma_bf16(D[mt][ntl], Ah[mt], Bh[np][q], Bh[np][q + 1]);
                mma_bf16(D[mt][ntl], Al[mt], Bh[np][q], Bh[np][q + 1]);
                mma_bf16(D[mt][ntl], Ah[mt], Bl[np][q], Bl[np][q + 1]);
            }
        }
    }

    // ---- initial domain barrier (instance 1) ----
    __syncthreads();
    if (tid == 0) { bar_arrive(d, gen0, 1u); bar_wait(d, gen0, 1u); }
    __syncthreads();

#pragma unroll 1
    for (int t = 0; t < Tv; t++) {
        const unsigned n1 = 2u + 2u * (unsigned)t;
        const unsigned n2 = 3u + 2u * (unsigned)t;

        // ---- stage h slice: 64 rows x 64k (bf16 hi/lo, swizzled) ----
        {
            const char* sh = (const char*)(g_hh + (size_t)(mrow0 + srow) * Hv + kbase) + soff;
            const char* sl = (const char*)(g_hl + (size_t)(mrow0 + srow) * Hv + kbase) + soff;
            uint4 h0 = __ldcg((const uint4*)sh + 0);
            uint4 h1 = __ldcg((const uint4*)sh + 1);
            uint4 l0 = __ldcg((const uint4*)sl + 0);
            uint4 l1 = __ldcg((const uint4*)sl + 1);
            *(uint4*)(sAhh + rb + ((soff +  0) ^ sws)) = h0;
            *(uint4*)(sAhh + rb + ((soff + 16) ^ sws)) = h1;
            *(uint4*)(sAhl + rb + ((soff +  0) ^ sws)) = l0;
            *(uint4*)(sAhl + rb + ((soff + 16) ^ sws)) = l1;
        }
        __syncthreads();

        // ---- rec-GEMM: D += h @ Wr (K=64, 4 ks, 3 terms) ----
#pragma unroll
        for (int ks = 0; ks < 4; ks++) {
            const uint32_t koffA = ((ks * 32) | khA) ^ sw;
            const uint32_t koffB = ((ks * 32) | khB) ^ sw;
            uint32_t Ah[2][4], Al[2][4], Bh[4][4], Bl[4][4];
#pragma unroll
            for (int mt = 0; mt < 2; mt++) {
                ldsm4(Ah[mt], aHiBase + mt * 2048 + koffA);
                ldsm4(Al[mt], aLoBase + mt * 2048 + koffA);
            }
#pragma unroll
            for (int np = 0; np < 4; np++) {
                ldsm4(Bh[np], bHiBase + np * 2048 + koffB);
                ldsm4(Bl[np], bLoBase + np * 2048 + koffB);
            }
#pragma unroll
            for (int mt = 0; mt < 2; mt++) {
#pragma unroll
                for (int ntl = 0; ntl < 8; ntl++) {
                    const int np = ntl >> 1, q = (ntl & 1) * 2;
                    mma_bf16(D[mt][ntl], Ah[mt], Bh[np][q], Bh[np][q + 1]);
                    mma_bf16(D[mt][ntl], Al[mt], Bh[np][q], Bh[np][q + 1]);
                    mma_bf16(D[mt][ntl], Ah[mt], Bl[np][q], Bl[np][q + 1]);
                }
            }
        }

        // ---- write split-K partials (global rows mrow0 + ...) ----
        {
            const int g = lid >> 2, c2 = (lid & 3) * 2;
            float* P = g_part[kc];
#pragma unroll
            for (int mt = 0; mt < 2; mt++) {
#pragma unroll
                for (int ntl = 0; ntl < 8; ntl++) {
                    int row0 = mrow0 + wm * 32 + mt * 16 + g;
                    int col = nbase + wn * 64 + ntl * 8 + c2;
                    float2 v0 = {D[mt][ntl][0], D[mt][ntl][1]};
                    float2 v1 = {D[mt][ntl][2], D[mt][ntl][3]};
                    *(float2*)&P[(size_t)row0 * Hv + col] = v0;
                    *(float2*)&P[(size_t)(row0 + 8) * Hv + col] = v1;
                }
            }
        }

        // ---- barrier 1: arrive early, x[t+1] work in the wait shadow ----
        __syncthreads();
        if (tid == 0) bar_arrive(d, gen0, n1);

        const uint32_t nbuf = (uint32_t)((t + 1) & 1) * 8192u;
        if (t + 1 < Tv) {
            const char* xh = (const char*)(g_xh + ((size_t)(t + 1) * Bv + mrow0 + srow) * Iv + xbase) + xoff;
            const char* xl = (const char*)(g_xl + ((size_t)(t + 1) * Bv + mrow0 + srow) * Iv + xbase) + xoff;
            uint4 a = __ldcg((const uint4*)xh);
            uint4 b = __ldcg((const uint4*)xl);
            *(uint4*)(sXhh + nbuf + rb + (xoff ^ sws)) = a;
            *(uint4*)(sXhl + nbuf + rb + (xoff ^ sws)) = b;
        }
        __syncthreads();   // sX[nbuf] visible CTA-wide

        // D = x[t+1] @ Wk  (independent of the domain barrier)
#pragma unroll
        for (int i = 0; i < 2; i++)
#pragma unroll
            for (int j = 0; j < 8; j++)
#pragma unroll
                for (int q = 0; q < 4; q++) D[i][j][q] = 0.f;
        if (t + 1 < Tv) {
#pragma unroll
            for (int ks = 0; ks < 2; ks++) {
                const uint32_t koffA = ((ks * 32) | khA) ^ sw;
                const uint32_t koffB = ((ks * 32) | khB) ^ sw;
                uint32_t Ah[2][4], Al[2][4], Bh[4][4], Bl[4][4];
#pragma unroll
                for (int mt = 0; mt < 2; mt++) {
                    ldsm4(Ah[mt], xHiBase + nbuf + mt * 2048 + koffA);
                    ldsm4(Al[mt], xLoBase + nbuf + mt * 2048 + koffA);
                }
#pragma unroll
                for (int np = 0; np < 4; np++) {
                    ldsm4(Bh[np], kHiBase + np * 2048 + koffB);
                    ldsm4(Bl[np], kLoBase + np * 2048 + koffB);
                }
#pragma unroll
                for (int mt = 0; mt < 2; mt++) {
#pragma unroll
                    for (int ntl = 0; ntl < 8; ntl++) {
                        const int np = ntl >> 1, q = (ntl & 1) * 2;
                        mma_bf16(D[mt][ntl], Ah[mt], Bh[np][q], Bh[np][q + 1]);
                        mma_bf16(D[mt][ntl], Al[mt], Bh[np][q], Bh[np][q + 1]);
                        mma_bf16(D[mt][ntl], Ah[mt], Bl[np][q], Bl[np][q + 1]);
                    }
                }
            }
        }

        // deferred wait
        if (tid == 0) bar_wait(d, gen0, n1);
        __syncthreads();

        // ---- phase 2: reduce 16 partials + bias + tanh -> h (this CTA's row) ----
        {
            float4 s = bb;
#pragma unroll
            for (int c = 0; c < KCHUNKS; c++) {
                float4 p = __ldcg((const float4*)&g_part[c][e]);
                s.x += p.x; s.y += p.y; s.z += p.z; s.w += p.w;
            }
            float h[4] = {tanhf(s.x), tanhf(s.y), tanhf(s.z), tanhf(s.w)};
            unsigned short hh[4], hl[4];
#pragma unroll
            for (int j = 0; j < 4; j++) {
                __nv_bfloat16 a = __float2bfloat16(h[j]);
                __nv_bfloat16 b = __float2bfloat16(h[j] - __bfloat162float(a));
                hh[j] = __bfloat16_as_ushort(a);
                hl[j] = __bfloat16_as_ushort(b);
            }
            *(ull*)&g_hh[e] = *(const ull*)hh;
            *(ull*)&g_hl[e] = *(const ull*)hl;
        }

        // ---- barrier 2 ----
        __syncthreads();
        if (tid == 0) { bar_arrive(d, gen0, n2); bar_wait(d, gen0, n2); }
        __syncthreads();
    }
}

// ============================================================
// Kernel C: out[b][o] = h_last[b][:] @ fc_w[:, o] + fc_b[o]
// ============================================================
__global__ void __launch_bounds__(256, 1) fc_kernel(
    const float* __restrict__ fcw, const float* __restrict__ fcb,
    float* __restrict__ out)
{
    __shared__ float hs[Hv];
    const int b = blockIdx.x;
    for (int i = threadIdx.x; i < Hv; i += 256) {
        hs[i] = __bfloat162float(g_hh[(size_t)b * Hv + i]) +
                __bfloat162float(g_hl[(size_t)b * Hv + i]);
    }
    __syncthreads();

    const int o = threadIdx.x;
    float a0 = 0.f, a1 = 0.f, a2 = 0.f, a3 = 0.f;
#pragma unroll 4
    for (int k = 0; k < Hv; k += 4) {
        a0 = fmaf(hs[k + 0], fcw[(size_t)(k + 0) * Ov + o], a0);
        a1 = fmaf(hs[k + 1], fcw[(size_t)(k + 1) * Ov + o], a1);
        a2 = fmaf(hs[k + 2], fcw[(size_t)(k + 2) * Ov + o], a2);
        a3 = fmaf(hs[k + 3], fcw[(size_t)(k + 3) * Ov + o], a3);
    }
    out[(size_t)b * Ov + o] = (a0 + a1) + (a2 + a3) + fcb[o];
}

// ============================================================
extern "C" void kernel_launch(void* const* d_in, const int* in_sizes, int n_in,
                              void* d_out, int out_size)
{
    const float* x   = (const float*)d_in[0];
    const float* wk  = (const float*)d_in[1];
    const float* wr  = (const float*)d_in[2];
    const float* bs  = (const float*)d_in[3];
    const float* fcw = (const float*)d_in[4];
    const float* fcb = (const float*)d_in[5];
    float* out = (float*)d_out;

    static int smem_set = 0;
    if (!smem_set) {
        cudaFuncSetAttribute(scan_kernel,
                             cudaFuncAttributeMaxDynamicSharedMemorySize, 180224);
        smem_set = 1;
    }

    size_t nx8 = (size_t)Bv * Tv * Iv / 8;
    split_x<<<(unsigned)((nx8 + 255) / 256), 256>>>(x);
    scan_kernel<<<NBLK_SCAN, 256, 180224>>>(wr, wk, bs);
    fc_kernel<<<Bv, 256>>>(fcw, fcb, out);
}